// round 1
// baseline (speedup 1.0000x reference)
#include <cuda_runtime.h>
#include <math.h>

// Problem constants (fixed instance)
#define NN 131072   // nodes
#define DD 128      // feature dim
#define GG 2048     // graphs
#define HH 512      // hidden
#define H4 2048     // 4*H
#define K2 1024     // 2*H (combined gemm K)

// ---------------- scratch (static device globals; no allocation) -------------
__device__ float d_Wc[H4 * K2];        // combined gate weights [4H, 2H]: W_ih[:, :H]+W_hh | W_ih[:, H:]
__device__ float d_bias[H4];           // b_ih + b_hh
__device__ float d_Wmt[DD * HH];       // W_m transposed: Wmt[d*512+k] = W_m[k*128+d]
__device__ float d_xc[GG * K2];        // q_star = [h | r] per graph, row stride 1024
__device__ float d_c[GG * HH];         // LSTM cell state
__device__ float d_gates[GG * H4];     // gates scratch
__device__ float d_u[GG * DD];         // u_g = W_m^T h_g
__device__ float d_beta[GG];           // b_m . h_g
__device__ float d_e[NN];              // per-node scores (then exp'd in place)
__device__ float d_s[GG * DD];         // s_g = sum_n a_n f_n
__device__ float d_tg[GG];             // t_g = exp_sum/(exp_sum+eps)
__device__ int   d_start[GG + 1];      // segment offsets

// ------------------------------ prep kernels --------------------------------
__global__ void prep_wc(const float* __restrict__ W_ih, const float* __restrict__ W_hh) {
    int idx = blockIdx.x * 256 + threadIdx.x;
    if (idx >= H4 * K2) return;
    int j = idx >> 10, k = idx & 1023;
    float v = W_ih[idx];
    if (k < HH) v += W_hh[j * HH + k];
    d_Wc[idx] = v;
}

__global__ void prep_misc(const float* __restrict__ b_ih, const float* __restrict__ b_hh,
                          const float* __restrict__ W_m) {
    int idx = blockIdx.x * 256 + threadIdx.x;
    if (idx < GG * HH) d_c[idx] = 0.0f;
    if (idx < H4)      d_bias[idx] = b_ih[idx] + b_hh[idx];
    if (idx < DD * HH) {
        int d = idx >> 9, k = idx & 511;
        d_Wmt[idx] = W_m[k * DD + d];
    }
}

__global__ void graph_offsets(const int* __restrict__ gi) {
    int g = blockIdx.x * 256 + threadIdx.x;
    if (g > GG) return;
    int lo = 0, hi = NN;
    while (lo < hi) { int mid = (lo + hi) >> 1; if (gi[mid] < g) lo = mid + 1; else hi = mid; }
    d_start[g] = lo;
}

// ---------------------- gates GEMM: gates = xc @ Wc^T + bias ----------------
// M=G=2048 (rows of xc), N=4H=2048 (rows of Wc), K=1024. 128x128 tile, 8x8/thread.
__global__ __launch_bounds__(256) void gemm_gates() {
    __shared__ __align__(16) float As[8][128];
    __shared__ __align__(16) float Bs[8][128];
    const int bm = blockIdx.y * 128, bn = blockIdx.x * 128;
    const int tid = threadIdx.x;
    const int lrow = tid >> 1;
    const int lk   = (tid & 1) * 4;
    const int tm = (tid >> 4) * 8;
    const int tn = (tid & 15) * 8;

    float acc[8][8];
#pragma unroll
    for (int i = 0; i < 8; i++)
#pragma unroll
        for (int j = 0; j < 8; j++) acc[i][j] = 0.0f;

    const float* A = d_xc;
    const float* B = d_Wc;

    for (int k0 = 0; k0 < K2; k0 += 8) {
        float4 a4 = *(const float4*)(A + (bm + lrow) * K2 + k0 + lk);
        float4 b4 = *(const float4*)(B + (bn + lrow) * K2 + k0 + lk);
        As[lk + 0][lrow] = a4.x; As[lk + 1][lrow] = a4.y;
        As[lk + 2][lrow] = a4.z; As[lk + 3][lrow] = a4.w;
        Bs[lk + 0][lrow] = b4.x; Bs[lk + 1][lrow] = b4.y;
        Bs[lk + 2][lrow] = b4.z; Bs[lk + 3][lrow] = b4.w;
        __syncthreads();
#pragma unroll
        for (int kk = 0; kk < 8; kk++) {
            float ar[8], br[8];
#pragma unroll
            for (int i = 0; i < 8; i++) ar[i] = As[kk][tm + i];
#pragma unroll
            for (int j = 0; j < 8; j++) br[j] = Bs[kk][tn + j];
#pragma unroll
            for (int i = 0; i < 8; i++)
#pragma unroll
                for (int j = 0; j < 8; j++) acc[i][j] += ar[i] * br[j];
        }
        __syncthreads();
    }
#pragma unroll
    for (int i = 0; i < 8; i++)
#pragma unroll
        for (int j = 0; j < 8; j++)
            d_gates[(bm + tm + i) * H4 + bn + tn + j] = acc[i][j] + d_bias[bn + tn + j];
}

// -------------------------------- LSTM cell ---------------------------------
__device__ __forceinline__ float sigmoidf_(float x) { return 1.0f / (1.0f + expf(-x)); }

__global__ void lstm_update(int use_gates) {
    int idx = blockIdx.x * 256 + threadIdx.x;       // G*H
    if (idx >= GG * HH) return;
    int g = idx >> 9, k = idx & 511;
    float ig, fg, gg, og;
    if (use_gates) {
        const float* row = d_gates + g * H4;
        ig = row[k]; fg = row[HH + k]; gg = row[2 * HH + k]; og = row[3 * HH + k];
    } else {
        ig = d_bias[k]; fg = d_bias[HH + k]; gg = d_bias[2 * HH + k]; og = d_bias[3 * HH + k];
    }
    float c = d_c[idx];
    c = sigmoidf_(fg) * c + sigmoidf_(ig) * tanhf(gg);
    float h = sigmoidf_(og) * tanhf(c);
    d_c[idx] = c;
    d_xc[g * K2 + k] = h;                            // h half of q_star
}

// ----------------------- u_g = W_m^T h_g  (16 graphs / block) ---------------
__global__ __launch_bounds__(128) void compute_u(const float* __restrict__ W_m) {
    int g0 = blockIdx.x * 16;
    int d = threadIdx.x;                             // 0..127
    float acc[16];
#pragma unroll
    for (int gg = 0; gg < 16; gg++) acc[gg] = 0.0f;
    __shared__ float hs[16][16];
    for (int k0 = 0; k0 < HH; k0 += 16) {
        int f1 = threadIdx.x;
        hs[f1 >> 4][f1 & 15] = d_xc[(g0 + (f1 >> 4)) * K2 + k0 + (f1 & 15)];
        int f2 = threadIdx.x + 128;
        hs[f2 >> 4][f2 & 15] = d_xc[(g0 + (f2 >> 4)) * K2 + k0 + (f2 & 15)];
        __syncthreads();
#pragma unroll
        for (int kk = 0; kk < 16; kk++) {
            float w = W_m[(k0 + kk) * DD + d];
#pragma unroll
            for (int gg = 0; gg < 16; gg++) acc[gg] += w * hs[gg][kk];
        }
        __syncthreads();
    }
#pragma unroll
    for (int gg = 0; gg < 16; gg++) d_u[(g0 + gg) * DD + d] = acc[gg];
}

// ------------------------------- beta = b_m . h ------------------------------
__global__ __launch_bounds__(128) void compute_beta(const float* __restrict__ b_m) {
    int g = blockIdx.x;
    int tid = threadIdx.x;
    float p = 0.0f;
    for (int k = tid; k < HH; k += 128) p += b_m[k] * d_xc[g * K2 + k];
    __shared__ float sh[128];
    sh[tid] = p; __syncthreads();
    for (int s = 64; s > 0; s >>= 1) { if (tid < s) sh[tid] += sh[tid + s]; __syncthreads(); }
    if (tid == 0) d_beta[g] = sh[0];
}

// ---------------- attention: scores + segment softmax + s_g ------------------
// one block (256 thr) per graph; graph_index is sorted -> contiguous segment
__global__ __launch_bounds__(256) void attention(const float* __restrict__ f) {
    int g = blockIdx.x;
    int s0 = d_start[g], s1 = d_start[g + 1];
    __shared__ __align__(16) float u_s[128];
    __shared__ float wred[8];
    __shared__ float emax_s, inv_s;
    __shared__ float sred[256];
    int tid = threadIdx.x, lane = tid & 31, warp = tid >> 5;

    if (tid < 128) u_s[tid] = d_u[g * DD + tid];
    float beta = d_beta[g];
    __syncthreads();

    // phase 1: e_n = f_n . u + beta, track max
    float4 uv = ((const float4*)u_s)[lane];
    float lmax = -3.4e38f;
    for (int n = s0 + warp; n < s1; n += 8) {
        float4 fv = ((const float4*)(f + (long)n * DD))[lane];
        float p = fv.x * uv.x + fv.y * uv.y + fv.z * uv.z + fv.w * uv.w;
        p += __shfl_xor_sync(0xffffffffu, p, 16);
        p += __shfl_xor_sync(0xffffffffu, p, 8);
        p += __shfl_xor_sync(0xffffffffu, p, 4);
        p += __shfl_xor_sync(0xffffffffu, p, 2);
        p += __shfl_xor_sync(0xffffffffu, p, 1);
        float e = p + beta;
        if (lane == 0) d_e[n] = e;
        lmax = fmaxf(lmax, e);
    }
    if (lane == 0) wred[warp] = lmax;
    __syncthreads();
    if (tid == 0) {
        float m = wred[0];
#pragma unroll
        for (int w = 1; w < 8; w++) m = fmaxf(m, wred[w]);
        emax_s = m;
    }
    __syncthreads();

    // phase 2: exp + sum
    float emax = emax_s;
    float lsum = 0.0f;
    for (int n = s0 + tid; n < s1; n += 256) {
        float ex = expf(fmaxf(d_e[n] - emax, -30.0f));
        d_e[n] = ex;
        lsum += ex;
    }
    sred[tid] = lsum; __syncthreads();
    for (int s = 128; s > 0; s >>= 1) { if (tid < s) sred[tid] += sred[tid + s]; __syncthreads(); }
    if (tid == 0) {
        float es = sred[0];
        float inv = 1.0f / (es + 1e-7f);
        inv_s = inv;
        d_tg[g] = es * inv;
    }
    __syncthreads();

    // phase 3: s_g[d] = sum_n a_n f[n,d]
    float inv = inv_s;
    int d = tid & 127, half = tid >> 7;
    float acc = 0.0f;
    for (int n = s0 + half; n < s1; n += 2) acc += (d_e[n] * inv) * f[(long)n * DD + d];
    sred[tid] = acc; __syncthreads();
    if (tid < 128) d_s[g * DD + tid] = sred[tid] + sred[tid + 128];
}

// ---------------- r_g = W_m s_g + t_g b_m  (8 graphs / block) ----------------
__global__ __launch_bounds__(512) void compute_r(const float* __restrict__ b_m) {
    int g0 = blockIdx.x * 8;
    int k = threadIdx.x;                              // 0..511
    __shared__ float ss[8][128];
    {
        int i = k;        ss[i >> 7][i & 127] = d_s[(g0 + (i >> 7)) * DD + (i & 127)];
        int i2 = k + 512; ss[i2 >> 7][i2 & 127] = d_s[(g0 + (i2 >> 7)) * DD + (i2 & 127)];
    }
    __syncthreads();
    float bm = b_m[k];
    float acc[8];
#pragma unroll
    for (int gg = 0; gg < 8; gg++) acc[gg] = d_tg[g0 + gg] * bm;
    for (int d = 0; d < DD; d++) {
        float w = d_Wmt[d * HH + k];
#pragma unroll
        for (int gg = 0; gg < 8; gg++) acc[gg] += w * ss[gg][d];
    }
#pragma unroll
    for (int gg = 0; gg < 8; gg++) d_xc[(g0 + gg) * K2 + HH + k] = acc[gg];
}

// ------------------------------ output copy ---------------------------------
__global__ void copy_out(float* __restrict__ out) {
    int idx = blockIdx.x * 256 + threadIdx.x;
    if (idx < GG * K2) out[idx] = d_xc[idx];
}

// ------------------------------ launcher ------------------------------------
extern "C" void kernel_launch(void* const* d_in, const int* in_sizes, int n_in,
                              void* d_out, int out_size) {
    const float* features = (const float*)d_in[0];
    const int*   gi       = (const int*)d_in[1];
    const float* W_m      = (const float*)d_in[2];
    const float* b_m      = (const float*)d_in[3];
    const float* W_ih     = (const float*)d_in[4];
    const float* W_hh     = (const float*)d_in[5];
    const float* b_ih     = (const float*)d_in[6];
    const float* b_hh     = (const float*)d_in[7];
    float* out = (float*)d_out;

    prep_wc<<<(H4 * K2) / 256, 256>>>(W_ih, W_hh);
    prep_misc<<<(GG * HH) / 256, 256>>>(b_ih, b_hh, W_m);
    graph_offsets<<<(GG + 1 + 255) / 256, 256>>>(gi);

    for (int t = 0; t < 3; t++) {
        if (t > 0) gemm_gates<<<dim3(H4 / 128, GG / 128), 256>>>();
        lstm_update<<<(GG * HH) / 256, 256>>>(t > 0 ? 1 : 0);
        compute_u<<<GG / 16, 128>>>(W_m);
        compute_beta<<<GG, 128>>>(b_m);
        attention<<<GG, 256>>>(features);
        compute_r<<<GG / 8, 512>>>(b_m);
    }
    copy_out<<<(GG * K2) / 256, 256>>>(out);
}

// round 2
// speedup vs baseline: 1.6373x; 1.6373x over previous
#include <cuda_runtime.h>
#include <math.h>

// Problem constants (fixed instance)
#define NN 131072   // nodes
#define DD 128      // feature dim
#define GG 2048     // graphs
#define HH 512      // hidden
#define H4 2048     // 4*H
#define K2 1024     // 2*H (combined gemm K)

// ---------------- scratch (static device globals; no allocation) -------------
__device__ float d_Wc[H4 * K2];        // combined gate weights [4H, 2H], tf32-rounded
__device__ float d_bias[H4];           // b_ih + b_hh
__device__ float d_Wmt[DD * HH];       // W_m transposed
__device__ float d_xc[GG * K2];        // q_star = [h | r] per graph (full fp32)
__device__ float d_xr[GG * K2];        // tf32-rounded copy of q_star (GEMM A operand)
__device__ float d_c[GG * HH];         // LSTM cell state
__device__ float d_gates[GG * H4];     // gates scratch
__device__ float d_u[GG * DD];         // u_g = W_m^T h_g
__device__ float d_beta[GG];           // b_m . h_g
__device__ float d_e[NN];              // per-node scores (then exp'd in place)
__device__ float d_s[GG * DD];         // s_g = sum_n a_n f_n
__device__ float d_tg[GG];             // t_g = exp_sum/(exp_sum+eps)
__device__ int   d_start[GG + 1];      // segment offsets

__device__ __forceinline__ unsigned f2tf(float x) {
    unsigned r;
    asm("cvt.rna.tf32.f32 %0, %1;" : "=r"(r) : "f"(x));
    return r;
}

// ------------------------------ prep kernels --------------------------------
__global__ void prep_wc(const float* __restrict__ W_ih, const float* __restrict__ W_hh) {
    int idx = blockIdx.x * 256 + threadIdx.x;
    if (idx >= H4 * K2) return;
    int j = idx >> 10, k = idx & 1023;
    float v = W_ih[idx];
    if (k < HH) v += W_hh[j * HH + k];
    d_Wc[idx] = __uint_as_float(f2tf(v));   // pre-rounded to tf32 (RN)
}

__global__ void prep_misc(const float* __restrict__ b_ih, const float* __restrict__ b_hh,
                          const float* __restrict__ W_m) {
    int idx = blockIdx.x * 256 + threadIdx.x;
    if (idx < GG * HH) d_c[idx] = 0.0f;
    if (idx < H4)      d_bias[idx] = b_ih[idx] + b_hh[idx];
    if (idx < DD * HH) {
        int d = idx >> 9, k = idx & 511;
        d_Wmt[idx] = W_m[k * DD + d];
    }
}

__global__ void graph_offsets(const int* __restrict__ gi) {
    int g = blockIdx.x * 256 + threadIdx.x;
    if (g > GG) return;
    int lo = 0, hi = NN;
    while (lo < hi) { int mid = (lo + hi) >> 1; if (gi[mid] < g) lo = mid + 1; else hi = mid; }
    d_start[g] = lo;
}

// ------------- gates GEMM (tf32 tensor cores): gates = xr @ Wc^T + bias ------
// M=2048, N=2048, K=1024. Block tile 128x128, BK=16, cp.async double buffer.
// 8 warps: warp_m in {0,1} (64 rows), warp_n in {0..3} (32 cols).
// Per warp: 4x4 grid of m16n8k8 mma tiles.
#define BK   16
#define SROW 20   // smem row stride (floats): conflict-free for fragment LDS

__device__ __forceinline__ void cpa16(float* smem_dst, const float* gsrc) {
    unsigned d = (unsigned)__cvta_generic_to_shared(smem_dst);
    asm volatile("cp.async.cg.shared.global [%0], [%1], 16;" :: "r"(d), "l"(gsrc));
}

__global__ __launch_bounds__(256, 2) void gemm_gates_tc() {
    __shared__ __align__(16) float As[2][128 * SROW];
    __shared__ __align__(16) float Bs[2][128 * SROW];
    const int bm = blockIdx.y * 128, bn = blockIdx.x * 128;
    const int tid = threadIdx.x, lane = tid & 31, warp = tid >> 5;
    const int wm = (warp & 1) * 64, wn = (warp >> 1) * 32;
    const int g = lane >> 2, t = lane & 3;

    // copy-stage indexing: thread covers float4 idx 2*tid, 2*tid+1
    const int crow = tid >> 1;
    const int ccol0 = ((2 * tid) & 3) * 4;   // 0 or 8

    float acc[4][4][4];
#pragma unroll
    for (int a = 0; a < 4; a++)
#pragma unroll
        for (int b = 0; b < 4; b++)
#pragma unroll
            for (int c = 0; c < 4; c++) acc[a][b][c] = 0.0f;

    // prologue: stage 0
    {
        int k0 = 0;
#pragma unroll
        for (int j = 0; j < 2; j++) {
            int c = ccol0 + j * 4;
            cpa16(&As[0][crow * SROW + c], d_xr + (bm + crow) * K2 + k0 + c);
            cpa16(&Bs[0][crow * SROW + c], d_Wc + (bn + crow) * K2 + k0 + c);
        }
        asm volatile("cp.async.commit_group;");
    }

    const int NIT = K2 / BK;   // 64
    for (int it = 0; it < NIT; it++) {
        int buf = it & 1;
        if (it + 1 < NIT) {
            int k0 = (it + 1) * BK, nb = buf ^ 1;
#pragma unroll
            for (int j = 0; j < 2; j++) {
                int c = ccol0 + j * 4;
                cpa16(&As[nb][crow * SROW + c], d_xr + (bm + crow) * K2 + k0 + c);
                cpa16(&Bs[nb][crow * SROW + c], d_Wc + (bn + crow) * K2 + k0 + c);
            }
            asm volatile("cp.async.commit_group;");
            asm volatile("cp.async.wait_group 1;");
        } else {
            asm volatile("cp.async.wait_group 0;");
        }
        __syncthreads();

#pragma unroll
        for (int kb = 0; kb < BK; kb += 8) {
            unsigned af[4][4], bf[4][2];
#pragma unroll
            for (int mi = 0; mi < 4; mi++) {
                const float* ba = &As[buf][(wm + mi * 16 + g) * SROW + kb + t];
                af[mi][0] = __float_as_uint(ba[0]);
                af[mi][1] = __float_as_uint(ba[8 * SROW]);
                af[mi][2] = __float_as_uint(ba[4]);
                af[mi][3] = __float_as_uint(ba[8 * SROW + 4]);
            }
#pragma unroll
            for (int ni = 0; ni < 4; ni++) {
                const float* bb = &Bs[buf][(wn + ni * 8 + g) * SROW + kb + t];
                bf[ni][0] = __float_as_uint(bb[0]);
                bf[ni][1] = __float_as_uint(bb[4]);
            }
#pragma unroll
            for (int mi = 0; mi < 4; mi++)
#pragma unroll
                for (int ni = 0; ni < 4; ni++)
                    asm volatile(
                        "mma.sync.aligned.m16n8k8.row.col.f32.tf32.tf32.f32 "
                        "{%0,%1,%2,%3}, {%4,%5,%6,%7}, {%8,%9}, {%0,%1,%2,%3};"
                        : "+f"(acc[mi][ni][0]), "+f"(acc[mi][ni][1]),
                          "+f"(acc[mi][ni][2]), "+f"(acc[mi][ni][3])
                        : "r"(af[mi][0]), "r"(af[mi][1]), "r"(af[mi][2]), "r"(af[mi][3]),
                          "r"(bf[ni][0]), "r"(bf[ni][1]));
        }
        __syncthreads();
    }

    // epilogue: add bias, store
#pragma unroll
    for (int mi = 0; mi < 4; mi++) {
        int r0 = bm + wm + mi * 16 + g;
#pragma unroll
        for (int ni = 0; ni < 4; ni++) {
            int cc = bn + wn + ni * 8 + 2 * t;
            float b0 = d_bias[cc], b1 = d_bias[cc + 1];
            float2 v0 = make_float2(acc[mi][ni][0] + b0, acc[mi][ni][1] + b1);
            float2 v1 = make_float2(acc[mi][ni][2] + b0, acc[mi][ni][3] + b1);
            *(float2*)&d_gates[(long)r0 * H4 + cc] = v0;
            *(float2*)&d_gates[(long)(r0 + 8) * H4 + cc] = v1;
        }
    }
}

// -------------------------------- LSTM cell ---------------------------------
__device__ __forceinline__ float sigmoidf_(float x) { return 1.0f / (1.0f + expf(-x)); }

__global__ void lstm_update(int use_gates) {
    int idx = blockIdx.x * 256 + threadIdx.x;       // G*H
    if (idx >= GG * HH) return;
    int g = idx >> 9, k = idx & 511;
    float ig, fg, gg, og;
    if (use_gates) {
        const float* row = d_gates + (long)g * H4;
        ig = row[k]; fg = row[HH + k]; gg = row[2 * HH + k]; og = row[3 * HH + k];
    } else {
        ig = d_bias[k]; fg = d_bias[HH + k]; gg = d_bias[2 * HH + k]; og = d_bias[3 * HH + k];
    }
    float c = d_c[idx];
    c = sigmoidf_(fg) * c + sigmoidf_(ig) * tanhf(gg);
    float h = sigmoidf_(og) * tanhf(c);
    d_c[idx] = c;
    d_xc[g * K2 + k] = h;                            // h half of q_star (fp32)
    d_xr[g * K2 + k] = __uint_as_float(f2tf(h));     // tf32-rounded for GEMM
}

// ----------------------- u_g = W_m^T h_g  (16 graphs / block) ---------------
__global__ __launch_bounds__(128) void compute_u(const float* __restrict__ W_m) {
    int g0 = blockIdx.x * 16;
    int d = threadIdx.x;                             // 0..127
    float acc[16];
#pragma unroll
    for (int gg = 0; gg < 16; gg++) acc[gg] = 0.0f;
    __shared__ float hs[16][16];
    for (int k0 = 0; k0 < HH; k0 += 16) {
        int f1 = threadIdx.x;
        hs[f1 >> 4][f1 & 15] = d_xc[(g0 + (f1 >> 4)) * K2 + k0 + (f1 & 15)];
        int f2 = threadIdx.x + 128;
        hs[f2 >> 4][f2 & 15] = d_xc[(g0 + (f2 >> 4)) * K2 + k0 + (f2 & 15)];
        __syncthreads();
#pragma unroll
        for (int kk = 0; kk < 16; kk++) {
            float w = W_m[(k0 + kk) * DD + d];
#pragma unroll
            for (int gg = 0; gg < 16; gg++) acc[gg] += w * hs[gg][kk];
        }
        __syncthreads();
    }
#pragma unroll
    for (int gg = 0; gg < 16; gg++) d_u[(g0 + gg) * DD + d] = acc[gg];
}

// ------------------------------- beta = b_m . h ------------------------------
__global__ __launch_bounds__(128) void compute_beta(const float* __restrict__ b_m) {
    int g = blockIdx.x;
    int tid = threadIdx.x;
    float p = 0.0f;
    for (int k = tid; k < HH; k += 128) p += b_m[k] * d_xc[g * K2 + k];
    __shared__ float sh[128];
    sh[tid] = p; __syncthreads();
    for (int s = 64; s > 0; s >>= 1) { if (tid < s) sh[tid] += sh[tid + s]; __syncthreads(); }
    if (tid == 0) d_beta[g] = sh[0];
}

// ---------------- attention: scores + segment softmax + s_g ------------------
__global__ __launch_bounds__(256) void attention(const float* __restrict__ f) {
    int g = blockIdx.x;
    int s0 = d_start[g], s1 = d_start[g + 1];
    __shared__ __align__(16) float u_s[128];
    __shared__ float wred[8];
    __shared__ float emax_s, inv_s;
    __shared__ float sred[256];
    int tid = threadIdx.x, lane = tid & 31, warp = tid >> 5;

    if (tid < 128) u_s[tid] = d_u[g * DD + tid];
    float beta = d_beta[g];
    __syncthreads();

    // phase 1: e_n = f_n . u + beta, track max
    float4 uv = ((const float4*)u_s)[lane];
    float lmax = -3.4e38f;
    for (int n = s0 + warp; n < s1; n += 8) {
        float4 fv = ((const float4*)(f + (long)n * DD))[lane];
        float p = fv.x * uv.x + fv.y * uv.y + fv.z * uv.z + fv.w * uv.w;
        p += __shfl_xor_sync(0xffffffffu, p, 16);
        p += __shfl_xor_sync(0xffffffffu, p, 8);
        p += __shfl_xor_sync(0xffffffffu, p, 4);
        p += __shfl_xor_sync(0xffffffffu, p, 2);
        p += __shfl_xor_sync(0xffffffffu, p, 1);
        float e = p + beta;
        if (lane == 0) d_e[n] = e;
        lmax = fmaxf(lmax, e);
    }
    if (lane == 0) wred[warp] = lmax;
    __syncthreads();
    if (tid == 0) {
        float m = wred[0];
#pragma unroll
        for (int w = 1; w < 8; w++) m = fmaxf(m, wred[w]);
        emax_s = m;
    }
    __syncthreads();

    // phase 2: exp + sum
    float emax = emax_s;
    float lsum = 0.0f;
    for (int n = s0 + tid; n < s1; n += 256) {
        float ex = expf(fmaxf(d_e[n] - emax, -30.0f));
        d_e[n] = ex;
        lsum += ex;
    }
    sred[tid] = lsum; __syncthreads();
    for (int s = 128; s > 0; s >>= 1) { if (tid < s) sred[tid] += sred[tid + s]; __syncthreads(); }
    if (tid == 0) {
        float es = sred[0];
        float inv = 1.0f / (es + 1e-7f);
        inv_s = inv;
        d_tg[g] = es * inv;
    }
    __syncthreads();

    // phase 3: s_g[d] = sum_n a_n f[n,d]
    float inv = inv_s;
    int d = tid & 127, half = tid >> 7;
    float acc = 0.0f;
    for (int n = s0 + half; n < s1; n += 2) acc += (d_e[n] * inv) * f[(long)n * DD + d];
    sred[tid] = acc; __syncthreads();
    if (tid < 128) d_s[g * DD + tid] = sred[tid] + sred[tid + 128];
}

// ---------------- r_g = W_m s_g + t_g b_m  (8 graphs / block) ----------------
__global__ __launch_bounds__(512) void compute_r(const float* __restrict__ b_m) {
    int g0 = blockIdx.x * 8;
    int k = threadIdx.x;                              // 0..511
    __shared__ float ss[8][128];
    {
        int i = k;        ss[i >> 7][i & 127] = d_s[(g0 + (i >> 7)) * DD + (i & 127)];
        int i2 = k + 512; ss[i2 >> 7][i2 & 127] = d_s[(g0 + (i2 >> 7)) * DD + (i2 & 127)];
    }
    __syncthreads();
    float bm = b_m[k];
    float acc[8];
#pragma unroll
    for (int gg = 0; gg < 8; gg++) acc[gg] = d_tg[g0 + gg] * bm;
    for (int d = 0; d < DD; d++) {
        float w = d_Wmt[d * HH + k];
#pragma unroll
        for (int gg = 0; gg < 8; gg++) acc[gg] += w * ss[gg][d];
    }
#pragma unroll
    for (int gg = 0; gg < 8; gg++) {
        d_xc[(g0 + gg) * K2 + HH + k] = acc[gg];
        d_xr[(g0 + gg) * K2 + HH + k] = __uint_as_float(f2tf(acc[gg]));
    }
}

// ------------------------------ output copy ---------------------------------
__global__ void copy_out(float* __restrict__ out) {
    int idx = blockIdx.x * 256 + threadIdx.x;
    if (idx < GG * K2) out[idx] = d_xc[idx];
}

// ------------------------------ launcher ------------------------------------
extern "C" void kernel_launch(void* const* d_in, const int* in_sizes, int n_in,
                              void* d_out, int out_size) {
    const float* features = (const float*)d_in[0];
    const int*   gi       = (const int*)d_in[1];
    const float* W_m      = (const float*)d_in[2];
    const float* b_m      = (const float*)d_in[3];
    const float* W_ih     = (const float*)d_in[4];
    const float* W_hh     = (const float*)d_in[5];
    const float* b_ih     = (const float*)d_in[6];
    const float* b_hh     = (const float*)d_in[7];
    float* out = (float*)d_out;

    prep_wc<<<(H4 * K2) / 256, 256>>>(W_ih, W_hh);
    prep_misc<<<(GG * HH) / 256, 256>>>(b_ih, b_hh, W_m);
    graph_offsets<<<(GG + 1 + 255) / 256, 256>>>(gi);

    for (int t = 0; t < 3; t++) {
        if (t > 0) gemm_gates_tc<<<dim3(H4 / 128, GG / 128), 256>>>();
        lstm_update<<<(GG * HH) / 256, 256>>>(t > 0 ? 1 : 0);
        compute_u<<<GG / 16, 128>>>(W_m);
        compute_beta<<<GG, 128>>>(b_m);
        attention<<<GG, 256>>>(features);
        compute_r<<<GG / 8, 512>>>(b_m);
    }
    copy_out<<<(GG * K2) / 256, 256>>>(out);
}

// round 4
// speedup vs baseline: 1.8542x; 1.1325x over previous
#include <cuda_runtime.h>
#include <cstdint>
#include <math.h>

// Problem constants (fixed instance)
#define NN 131072   // nodes
#define DD 128      // feature dim
#define GG 2048     // graphs
#define HH 512      // hidden
#define H4 2048     // 4*H
#define K2 1024     // 2*H (combined gemm K)

// ---------------- scratch (static device globals; no allocation) -------------
__device__ float d_Wc[H4 * K2];        // combined gate weights [4H, 2H], tf32-rounded
__device__ float d_bias[H4];           // b_ih + b_hh
__device__ float d_gbias[H4];          // bias + h0 @ Wc[:, :H]^T  (t=1 shared part)
__device__ float d_Wmt[DD * HH];       // W_m transposed
__device__ float d_xc[GG * K2];        // q_star = [h | r] per graph (full fp32)
__device__ float d_xr[GG * K2];        // tf32-rounded copy of q_star (GEMM A operand)
__device__ float d_c[GG * HH];         // LSTM cell state
__device__ float d_gates[GG * H4];     // gates scratch
__device__ float d_u[GG * DD];         // u_g = W_m^T h_g
__device__ float d_beta[GG];           // b_m . h_g
__device__ float d_s[GG * DD];         // s_g = sum_n a_n f_n
__device__ float d_tg[GG];             // t_g = exp_sum/(exp_sum+eps)
__device__ int   d_start[GG + 1];      // segment offsets

__device__ __forceinline__ unsigned f2tf(float x) {
    unsigned r;
    asm("cvt.rna.tf32.f32 %0, %1;" : "=r"(r) : "f"(x));
    return r;
}

// ------------------------------ prep kernels --------------------------------
__global__ void prep_wc(const float* __restrict__ W_ih, const float* __restrict__ W_hh) {
    int idx = blockIdx.x * 256 + threadIdx.x;
    if (idx >= H4 * K2) return;
    int j = idx >> 10, k = idx & 1023;
    float v = W_ih[idx];
    if (k < HH) v += W_hh[j * HH + k];
    d_Wc[idx] = __uint_as_float(f2tf(v));   // pre-rounded to tf32 (RN)
}

__global__ void prep_misc(const float* __restrict__ b_ih, const float* __restrict__ b_hh,
                          const float* __restrict__ W_m) {
    int idx = blockIdx.x * 256 + threadIdx.x;
    if (idx < GG * HH) d_c[idx] = 0.0f;
    if (idx < H4)      d_bias[idx] = b_ih[idx] + b_hh[idx];
    if (idx < DD * HH) {
        int d = idx >> 9, k = idx & 511;
        d_Wmt[idx] = W_m[k * DD + d];
    }
}

__global__ void graph_offsets(const int* __restrict__ gi) {
    int g = blockIdx.x * 256 + threadIdx.x;
    if (g > GG) return;
    int lo = 0, hi = NN;
    while (lo < hi) { int mid = (lo + hi) >> 1; if (gi[mid] < g) lo = mid + 1; else hi = mid; }
    d_start[g] = lo;
}

// gbias[j] = bias[j] + sum_{k<H} h0[k] * Wc[j,k]  (h0 identical across graphs)
__global__ __launch_bounds__(256) void compute_gbias() {
    int j = blockIdx.x * 8 + (threadIdx.x >> 5);
    int lane = threadIdx.x & 31;
    const float* w = d_Wc + (size_t)j * K2;
    const float* h0 = d_xc;                          // graph 0 h part
    float p = 0.0f;
#pragma unroll
    for (int k0 = 0; k0 < HH; k0 += 128) {
        float4 wv = *(const float4*)(w + k0 + lane * 4);
        float4 hv = *(const float4*)(h0 + k0 + lane * 4);
        p += wv.x * hv.x + wv.y * hv.y + wv.z * hv.z + wv.w * hv.w;
    }
    p += __shfl_xor_sync(0xffffffffu, p, 16);
    p += __shfl_xor_sync(0xffffffffu, p, 8);
    p += __shfl_xor_sync(0xffffffffu, p, 4);
    p += __shfl_xor_sync(0xffffffffu, p, 2);
    p += __shfl_xor_sync(0xffffffffu, p, 1);
    if (lane == 0) d_gbias[j] = d_bias[j] + p;
}

// --------- gates GEMM (tf32 mma.sync): gates = xr[:,KOFF:] @ Wc[:,KOFF:]^T + bias
// CTA tile 128(M) x 256(N), BK=16, double-buffered cp.async.
// 8 warps, warp tile 64x64 (wm=(warp&1)*64, wn=(warp>>1)*64), 4x8 m16n8k8 tiles.
#define SROW 20   // smem row stride (floats): conflict-free fragment LDS
#define A_STG 2560   // 128*20 floats per stage
#define B_STG 5120   // 256*20 floats per stage
#define GEMM_SMEM ((2 * A_STG + 2 * B_STG) * 4)

__device__ __forceinline__ void cpa16(uint32_t daddr, const float* g) {
    asm volatile("cp.async.cg.shared.global [%0], [%1], 16;" :: "r"(daddr), "l"(g));
}

__device__ __forceinline__ void load_stage(uint32_t sA, uint32_t sB,
                                           int bm, int bn, int k0, int tid) {
#pragma unroll
    for (int j = 0; j < 2; j++) {
        int a = tid + j * 256;
        int row = a >> 2, c = a & 3;
        cpa16(sA + (uint32_t)(row * SROW + c * 4) * 4,
              d_xr + (size_t)(bm + row) * K2 + k0 + c * 4);
    }
#pragma unroll
    for (int j = 0; j < 4; j++) {
        int b = tid + j * 256;
        int row = b >> 2, c = b & 3;
        cpa16(sB + (uint32_t)(row * SROW + c * 4) * 4,
              d_Wc + (size_t)(bn + row) * K2 + k0 + c * 4);
    }
    asm volatile("cp.async.commit_group;");
}

template <int KOFF, int KLEN, bool GB>
__global__ __launch_bounds__(256, 1) void gemm_tc() {
    extern __shared__ float sm[];
    float* Abase = sm;                 // 2 stages of A
    float* Bbase = sm + 2 * A_STG;     // 2 stages of B
    uint32_t sAu, sBu;
    {
        uint64_t t;
        asm("cvta.to.shared.u64 %0, %1;" : "=l"(t) : "l"(Abase));
        sAu = (uint32_t)t;
        asm("cvta.to.shared.u64 %0, %1;" : "=l"(t) : "l"(Bbase));
        sBu = (uint32_t)t;
    }
    const int tid = threadIdx.x, lane = tid & 31, warp = tid >> 5;
    const int wm = (warp & 1) * 64, wn = (warp >> 1) * 64;
    const int g = lane >> 2, t = lane & 3;
    const int bm = blockIdx.y * 128, bn = blockIdx.x * 256;

    float acc[4][8][4];
#pragma unroll
    for (int a = 0; a < 4; a++)
#pragma unroll
        for (int b = 0; b < 8; b++)
#pragma unroll
            for (int c = 0; c < 4; c++) acc[a][b][c] = 0.0f;

    load_stage(sAu, sBu, bm, bn, KOFF, tid);

    const int NIT = KLEN / 16;
    for (int it = 0; it < NIT; it++) {
        int buf = it & 1;
        if (it + 1 < NIT) {
            int nb = buf ^ 1;
            load_stage(sAu + nb * A_STG * 4, sBu + nb * B_STG * 4,
                       bm, bn, KOFF + (it + 1) * 16, tid);
            asm volatile("cp.async.wait_group 1;");
        } else {
            asm volatile("cp.async.wait_group 0;");
        }
        __syncthreads();

        const float* Ab = Abase + buf * A_STG;
        const float* Bb = Bbase + buf * B_STG;
#pragma unroll
        for (int kb = 0; kb < 16; kb += 8) {
            unsigned af[4][4], bf[8][2];
#pragma unroll
            for (int mi = 0; mi < 4; mi++) {
                const float* ba = &Ab[(wm + mi * 16 + g) * SROW + kb + t];
                af[mi][0] = __float_as_uint(ba[0]);
                af[mi][1] = __float_as_uint(ba[8 * SROW]);
                af[mi][2] = __float_as_uint(ba[4]);
                af[mi][3] = __float_as_uint(ba[8 * SROW + 4]);
            }
#pragma unroll
            for (int ni = 0; ni < 8; ni++) {
                const float* bb = &Bb[(wn + ni * 8 + g) * SROW + kb + t];
                bf[ni][0] = __float_as_uint(bb[0]);
                bf[ni][1] = __float_as_uint(bb[4]);
            }
#pragma unroll
            for (int mi = 0; mi < 4; mi++)
#pragma unroll
                for (int ni = 0; ni < 8; ni++)
                    asm volatile(
                        "mma.sync.aligned.m16n8k8.row.col.f32.tf32.tf32.f32 "
                        "{%0,%1,%2,%3}, {%4,%5,%6,%7}, {%8,%9}, {%0,%1,%2,%3};"
                        : "+f"(acc[mi][ni][0]), "+f"(acc[mi][ni][1]),
                          "+f"(acc[mi][ni][2]), "+f"(acc[mi][ni][3])
                        : "r"(af[mi][0]), "r"(af[mi][1]), "r"(af[mi][2]), "r"(af[mi][3]),
                          "r"(bf[ni][0]), "r"(bf[ni][1]));
        }
        __syncthreads();
    }

    const float* bias = GB ? d_gbias : d_bias;
#pragma unroll
    for (int mi = 0; mi < 4; mi++) {
        int r0 = bm + wm + mi * 16 + g;
#pragma unroll
        for (int ni = 0; ni < 8; ni++) {
            int cc = bn + wn + ni * 8 + 2 * t;
            float b0 = bias[cc], b1 = bias[cc + 1];
            float2 v0 = make_float2(acc[mi][ni][0] + b0, acc[mi][ni][1] + b1);
            float2 v1 = make_float2(acc[mi][ni][2] + b0, acc[mi][ni][3] + b1);
            *(float2*)&d_gates[(size_t)r0 * H4 + cc] = v0;
            *(float2*)&d_gates[(size_t)(r0 + 8) * H4 + cc] = v1;
        }
    }
}

// -------------------------------- LSTM cell ---------------------------------
__device__ __forceinline__ float sigmoidf_(float x) { return 1.0f / (1.0f + expf(-x)); }

__global__ void lstm_update(int use_gates, float* __restrict__ out, int wout) {
    int idx = blockIdx.x * 256 + threadIdx.x;       // G*H
    if (idx >= GG * HH) return;
    int g = idx >> 9, k = idx & 511;
    float ig, fg, gg, og;
    if (use_gates) {
        const float* row = d_gates + (size_t)g * H4;
        ig = row[k]; fg = row[HH + k]; gg = row[2 * HH + k]; og = row[3 * HH + k];
    } else {
        ig = d_bias[k]; fg = d_bias[HH + k]; gg = d_bias[2 * HH + k]; og = d_bias[3 * HH + k];
    }
    float c = d_c[idx];
    c = sigmoidf_(fg) * c + sigmoidf_(ig) * tanhf(gg);
    float h = sigmoidf_(og) * tanhf(c);
    d_c[idx] = c;
    d_xc[g * K2 + k] = h;                            // h half of q_star (fp32)
    d_xr[g * K2 + k] = __uint_as_float(f2tf(h));     // tf32-rounded for GEMM
    if (wout) out[g * K2 + k] = h;                   // final-iter output h half
}

// ----------------------- u_g = W_m^T h_g  (16 graphs / block) ---------------
__global__ __launch_bounds__(128) void compute_u(const float* __restrict__ W_m) {
    int g0 = blockIdx.x * 16;
    int d = threadIdx.x;                             // 0..127
    float acc[16];
#pragma unroll
    for (int gg = 0; gg < 16; gg++) acc[gg] = 0.0f;
    __shared__ float hs[16][16];
    for (int k0 = 0; k0 < HH; k0 += 16) {
        int f1 = threadIdx.x;
        hs[f1 >> 4][f1 & 15] = d_xc[(g0 + (f1 >> 4)) * K2 + k0 + (f1 & 15)];
        int f2 = threadIdx.x + 128;
        hs[f2 >> 4][f2 & 15] = d_xc[(g0 + (f2 >> 4)) * K2 + k0 + (f2 & 15)];
        __syncthreads();
#pragma unroll
        for (int kk = 0; kk < 16; kk++) {
            float w = W_m[(k0 + kk) * DD + d];
#pragma unroll
            for (int gg = 0; gg < 16; gg++) acc[gg] += w * hs[gg][kk];
        }
        __syncthreads();
    }
#pragma unroll
    for (int gg = 0; gg < 16; gg++) d_u[(g0 + gg) * DD + d] = acc[gg];
}

// ------------------------------- beta = b_m . h ------------------------------
__global__ __launch_bounds__(128) void compute_beta(const float* __restrict__ b_m) {
    int g = blockIdx.x;
    int tid = threadIdx.x;
    float p = 0.0f;
    for (int k = tid; k < HH; k += 128) p += b_m[k] * d_xc[g * K2 + k];
    __shared__ float sh[128];
    sh[tid] = p; __syncthreads();
    for (int s = 64; s > 0; s >>= 1) { if (tid < s) sh[tid] += sh[tid + s]; __syncthreads(); }
    if (tid == 0) d_beta[g] = sh[0];
}

// ------- fused attention: single pass online softmax + weighted feature sum --
// one block (256 thr / 8 warps) per graph; segments contiguous (sorted index)
__global__ __launch_bounds__(256) void attention_fused(const float* __restrict__ f) {
    int g = blockIdx.x;
    int s0 = d_start[g], s1 = d_start[g + 1];
    __shared__ __align__(16) float u_s[128];
    __shared__ __align__(16) float wacc[8][128];
    __shared__ float wm_s[8], wS_s[8], fac_s[8];
    __shared__ float inv_s;
    int tid = threadIdx.x, lane = tid & 31, warp = tid >> 5;

    if (tid < 128) u_s[tid] = d_u[g * DD + tid];
    float beta = d_beta[g];
    __syncthreads();

    float4 uv = ((const float4*)u_s)[lane];
    float m = -3.4e38f, S = 0.0f;
    float4 acc = make_float4(0.f, 0.f, 0.f, 0.f);

    for (int n = s0 + warp; n < s1; n += 8) {
        float4 fv = *(const float4*)(f + (size_t)n * DD + lane * 4);
        float p = fv.x * uv.x + fv.y * uv.y + fv.z * uv.z + fv.w * uv.w;
        p += __shfl_xor_sync(0xffffffffu, p, 16);
        p += __shfl_xor_sync(0xffffffffu, p, 8);
        p += __shfl_xor_sync(0xffffffffu, p, 4);
        p += __shfl_xor_sync(0xffffffffu, p, 2);
        p += __shfl_xor_sync(0xffffffffu, p, 1);
        float e = p + beta;
        float mn = fmaxf(m, e);
        float alpha = expf(m - mn);      // exp(-inf)=0 on first node
        float w = expf(e - mn);
        S = S * alpha + w;
        acc.x = acc.x * alpha + w * fv.x;
        acc.y = acc.y * alpha + w * fv.y;
        acc.z = acc.z * alpha + w * fv.z;
        acc.w = acc.w * alpha + w * fv.w;
        m = mn;
    }
    if (lane == 0) { wm_s[warp] = m; wS_s[warp] = S; }
    ((float4*)wacc[warp])[lane] = acc;
    __syncthreads();

    if (tid == 0) {
        float M = -3.4e38f;
#pragma unroll
        for (int w = 0; w < 8; w++)
            if (wS_s[w] > 0.0f) M = fmaxf(M, wm_s[w]);
        float Z = 0.0f;
#pragma unroll
        for (int w = 0; w < 8; w++) {
            float sc = (wS_s[w] > 0.0f) ? expf(wm_s[w] - M) : 0.0f;
            fac_s[w] = sc;
            Z += sc * wS_s[w];
        }
        float inv = 1.0f / (Z + 1e-7f);
        inv_s = inv;
        d_tg[g] = Z * inv;
    }
    __syncthreads();

    if (tid < 128) {
        float inv = inv_s;
        float s = 0.0f;
#pragma unroll
        for (int w = 0; w < 8; w++) s += wacc[w][tid] * fac_s[w];
        d_s[g * DD + tid] = s * inv;
    }
}

// ---------------- r_g = W_m s_g + t_g b_m  (8 graphs / block) ----------------
__global__ __launch_bounds__(512) void compute_r(const float* __restrict__ b_m,
                                                 float* __restrict__ out, int wout) {
    int g0 = blockIdx.x * 8;
    int k = threadIdx.x;                              // 0..511
    __shared__ float ss[8][128];
    {
        int i = k;        ss[i >> 7][i & 127] = d_s[(g0 + (i >> 7)) * DD + (i & 127)];
        int i2 = k + 512; ss[i2 >> 7][i2 & 127] = d_s[(g0 + (i2 >> 7)) * DD + (i2 & 127)];
    }
    __syncthreads();
    float bm = b_m[k];
    float acc[8];
#pragma unroll
    for (int gg = 0; gg < 8; gg++) acc[gg] = d_tg[g0 + gg] * bm;
    for (int d = 0; d < DD; d++) {
        float w = d_Wmt[d * HH + k];
#pragma unroll
        for (int gg = 0; gg < 8; gg++) acc[gg] += w * ss[gg][d];
    }
#pragma unroll
    for (int gg = 0; gg < 8; gg++) {
        d_xc[(g0 + gg) * K2 + HH + k] = acc[gg];
        d_xr[(g0 + gg) * K2 + HH + k] = __uint_as_float(f2tf(acc[gg]));
        if (wout) out[(g0 + gg) * K2 + HH + k] = acc[gg];
    }
}

// ------------------------------ launcher ------------------------------------
extern "C" void kernel_launch(void* const* d_in, const int* in_sizes, int n_in,
                              void* d_out, int out_size) {
    const float* features = (const float*)d_in[0];
    const int*   gi       = (const int*)d_in[1];
    const float* W_m      = (const float*)d_in[2];
    const float* b_m      = (const float*)d_in[3];
    const float* W_ih     = (const float*)d_in[4];
    const float* W_hh     = (const float*)d_in[5];
    const float* b_ih     = (const float*)d_in[6];
    const float* b_hh     = (const float*)d_in[7];
    float* out = (float*)d_out;

    cudaFuncSetAttribute(gemm_tc<512, 512, true>,
                         cudaFuncAttributeMaxDynamicSharedMemorySize, GEMM_SMEM);
    cudaFuncSetAttribute(gemm_tc<0, 1024, false>,
                         cudaFuncAttributeMaxDynamicSharedMemorySize, GEMM_SMEM);

    prep_wc<<<(H4 * K2) / 256, 256>>>(W_ih, W_hh);
    prep_misc<<<(GG * HH) / 256, 256>>>(b_ih, b_hh, W_m);
    graph_offsets<<<(GG + 1 + 255) / 256, 256>>>(gi);

    for (int t = 0; t < 3; t++) {
        if (t == 1) {
            compute_gbias<<<GG / 8, 256>>>();
            gemm_tc<512, 512, true><<<dim3(H4 / 256, GG / 128), 256, GEMM_SMEM>>>();
        } else if (t == 2) {
            gemm_tc<0, 1024, false><<<dim3(H4 / 256, GG / 128), 256, GEMM_SMEM>>>();
        }
        int wout = (t == 2) ? 1 : 0;
        lstm_update<<<(GG * HH) / 256, 256>>>(t > 0 ? 1 : 0, out, wout);
        compute_u<<<GG / 16, 128>>>(W_m);
        compute_beta<<<GG, 128>>>(b_m);
        attention_fused<<<GG, 256>>>(features);
        compute_r<<<GG / 8, 512>>>(b_m, out, wout);
    }
}

// round 5
// speedup vs baseline: 2.5823x; 1.3926x over previous
#include <cuda_runtime.h>
#include <cuda_fp16.h>
#include <cstdint>
#include <math.h>

// Problem constants (fixed instance)
#define NN 131072   // nodes
#define DD 128      // feature dim
#define GG 2048     // graphs
#define HH 512      // hidden
#define H4 2048     // 4*H
#define K2 1024     // 2*H (combined gemm K)

// ---------------- scratch (static device globals; no allocation) -------------
__device__ __half d_Wch[H4 * K2];      // combined gate weights [4H, 2H], fp16
__device__ float d_bias[H4];           // b_ih + b_hh
__device__ float d_gbias[H4];          // bias + h0 @ Wc[:, :H]^T  (t=1 shared part)
__device__ float d_Wmt[DD * HH];       // W_m transposed
__device__ float d_xc[GG * K2];        // q_star = [h | r] per graph (full fp32)
__device__ __half d_xh[GG * K2];       // fp16 copy of q_star (GEMM A operand)
__device__ float d_c[GG * HH];         // LSTM cell state
__device__ float d_gates[GG * H4];     // gates scratch
__device__ float d_u[GG * DD];         // u_g = W_m^T h_g
__device__ float d_beta[GG];           // b_m . h_g
__device__ float d_s[GG * DD];         // s_g = sum_n a_n f_n
__device__ float d_tg[GG];             // t_g = exp_sum/(exp_sum+eps)
__device__ int   d_start[GG + 1];      // segment offsets

// ------------------------------ prep kernels --------------------------------
__global__ void prep_wc(const float* __restrict__ W_ih, const float* __restrict__ W_hh) {
    int idx = blockIdx.x * 256 + threadIdx.x;
    if (idx >= H4 * K2) return;
    int j = idx >> 10, k = idx & 1023;
    float v = W_ih[idx];
    if (k < HH) v += W_hh[j * HH + k];
    d_Wch[idx] = __float2half(v);
}

__global__ void prep_misc(const float* __restrict__ b_ih, const float* __restrict__ b_hh,
                          const float* __restrict__ W_m) {
    int idx = blockIdx.x * 256 + threadIdx.x;
    if (idx < GG * HH) d_c[idx] = 0.0f;
    if (idx < H4)      d_bias[idx] = b_ih[idx] + b_hh[idx];
    if (idx < DD * HH) {
        int d = idx >> 9, k = idx & 511;
        d_Wmt[idx] = W_m[k * DD + d];
    }
}

__global__ void graph_offsets(const int* __restrict__ gi) {
    int g = blockIdx.x * 256 + threadIdx.x;
    if (g > GG) return;
    int lo = 0, hi = NN;
    while (lo < hi) { int mid = (lo + hi) >> 1; if (gi[mid] < g) lo = mid + 1; else hi = mid; }
    d_start[g] = lo;
}

// gbias[j] = bias[j] + sum_{k<H} h0[k] * Wc[j,k]  (h0 identical across graphs)
__global__ __launch_bounds__(256) void compute_gbias() {
    int j = blockIdx.x * 8 + (threadIdx.x >> 5);
    int lane = threadIdx.x & 31;
    const __half2* w2 = (const __half2*)(d_Wch + (size_t)j * K2);
    const float2* h02 = (const float2*)d_xc;          // graph 0 h part
    float p = 0.0f;
#pragma unroll
    for (int i = lane; i < HH / 2; i += 32) {
        float2 wf = __half22float2(w2[i]);
        float2 hf = h02[i];
        p += wf.x * hf.x + wf.y * hf.y;
    }
    p += __shfl_xor_sync(0xffffffffu, p, 16);
    p += __shfl_xor_sync(0xffffffffu, p, 8);
    p += __shfl_xor_sync(0xffffffffu, p, 4);
    p += __shfl_xor_sync(0xffffffffu, p, 2);
    p += __shfl_xor_sync(0xffffffffu, p, 1);
    if (lane == 0) d_gbias[j] = d_bias[j] + p;
}

// --------- gates GEMM (fp16 mma.sync m16n8k16): gates = xh @ Wch^T + bias ----
// CTA tile 128(M) x 256(N), BK=32 halves, double-buffered cp.async.
// 8 warps, warp tile 64x64, 4x8 m16n8k16 tiles, fp32 accumulate.
#define SROWH 40      // smem row stride in halves (conflict-free fragment LDS)
#define A_STGH (128 * SROWH)   // halves per A stage
#define B_STGH (256 * SROWH)   // halves per B stage
#define GEMM_SMEM ((2 * A_STGH + 2 * B_STGH) * 2)

__device__ __forceinline__ void cpa16(uint32_t daddr, const void* g) {
    asm volatile("cp.async.cg.shared.global [%0], [%1], 16;" :: "r"(daddr), "l"(g));
}

__device__ __forceinline__ void load_stage(uint32_t sA, uint32_t sB,
                                           int bm, int bn, int k0, int tid) {
#pragma unroll
    for (int j = 0; j < 2; j++) {
        int a = tid + j * 256;
        int row = a >> 2, c = a & 3;
        cpa16(sA + (uint32_t)(row * SROWH + c * 8) * 2,
              d_xh + (size_t)(bm + row) * K2 + k0 + c * 8);
    }
#pragma unroll
    for (int j = 0; j < 4; j++) {
        int b = tid + j * 256;
        int row = b >> 2, c = b & 3;
        cpa16(sB + (uint32_t)(row * SROWH + c * 8) * 2,
              d_Wch + (size_t)(bn + row) * K2 + k0 + c * 8);
    }
    asm volatile("cp.async.commit_group;");
}

template <int KOFF, int KLEN, bool GB>
__global__ __launch_bounds__(256, 1) void gemm_h() {
    extern __shared__ __half smh[];
    __half* Abase = smh;                    // 2 stages of A
    __half* Bbase = smh + 2 * A_STGH;       // 2 stages of B
    uint32_t sAu, sBu;
    {
        uint64_t t;
        asm("cvta.to.shared.u64 %0, %1;" : "=l"(t) : "l"(Abase));
        sAu = (uint32_t)t;
        asm("cvta.to.shared.u64 %0, %1;" : "=l"(t) : "l"(Bbase));
        sBu = (uint32_t)t;
    }
    const int tid = threadIdx.x, lane = tid & 31, warp = tid >> 5;
    const int wm = (warp & 1) * 64, wn = (warp >> 1) * 64;
    const int g = lane >> 2, t = lane & 3;
    const int bm = blockIdx.y * 128, bn = blockIdx.x * 256;

    float acc[4][8][4];
#pragma unroll
    for (int a = 0; a < 4; a++)
#pragma unroll
        for (int b = 0; b < 8; b++)
#pragma unroll
            for (int c = 0; c < 4; c++) acc[a][b][c] = 0.0f;

    load_stage(sAu, sBu, bm, bn, KOFF, tid);

    const int NIT = KLEN / 32;
    for (int it = 0; it < NIT; it++) {
        int buf = it & 1;
        if (it + 1 < NIT) {
            int nb = buf ^ 1;
            load_stage(sAu + nb * A_STGH * 2, sBu + nb * B_STGH * 2,
                       bm, bn, KOFF + (it + 1) * 32, tid);
            asm volatile("cp.async.wait_group 1;");
        } else {
            asm volatile("cp.async.wait_group 0;");
        }
        __syncthreads();

        const __half* Ab = Abase + buf * A_STGH;
        const __half* Bb = Bbase + buf * B_STGH;
#pragma unroll
        for (int kb = 0; kb < 32; kb += 16) {
            unsigned af[4][4], bf[8][2];
#pragma unroll
            for (int mi = 0; mi < 4; mi++) {
                const __half* ba = &Ab[(wm + mi * 16 + g) * SROWH + kb + 2 * t];
                af[mi][0] = *(const uint32_t*)(ba);
                af[mi][1] = *(const uint32_t*)(ba + 8 * SROWH);
                af[mi][2] = *(const uint32_t*)(ba + 8);
                af[mi][3] = *(const uint32_t*)(ba + 8 * SROWH + 8);
            }
#pragma unroll
            for (int ni = 0; ni < 8; ni++) {
                const __half* bb = &Bb[(wn + ni * 8 + g) * SROWH + kb + 2 * t];
                bf[ni][0] = *(const uint32_t*)(bb);
                bf[ni][1] = *(const uint32_t*)(bb + 8);
            }
#pragma unroll
            for (int mi = 0; mi < 4; mi++)
#pragma unroll
                for (int ni = 0; ni < 8; ni++)
                    asm volatile(
                        "mma.sync.aligned.m16n8k16.row.col.f32.f16.f16.f32 "
                        "{%0,%1,%2,%3}, {%4,%5,%6,%7}, {%8,%9}, {%0,%1,%2,%3};"
                        : "+f"(acc[mi][ni][0]), "+f"(acc[mi][ni][1]),
                          "+f"(acc[mi][ni][2]), "+f"(acc[mi][ni][3])
                        : "r"(af[mi][0]), "r"(af[mi][1]), "r"(af[mi][2]), "r"(af[mi][3]),
                          "r"(bf[ni][0]), "r"(bf[ni][1]));
        }
        __syncthreads();
    }

    const float* bias = GB ? d_gbias : d_bias;
#pragma unroll
    for (int mi = 0; mi < 4; mi++) {
        int r0 = bm + wm + mi * 16 + g;
#pragma unroll
        for (int ni = 0; ni < 8; ni++) {
            int cc = bn + wn + ni * 8 + 2 * t;
            float b0 = bias[cc], b1 = bias[cc + 1];
            float2 v0 = make_float2(acc[mi][ni][0] + b0, acc[mi][ni][1] + b1);
            float2 v1 = make_float2(acc[mi][ni][2] + b0, acc[mi][ni][3] + b1);
            *(float2*)&d_gates[(size_t)r0 * H4 + cc] = v0;
            *(float2*)&d_gates[(size_t)(r0 + 8) * H4 + cc] = v1;
        }
    }
}

// -------------------------------- LSTM cell ---------------------------------
__device__ __forceinline__ float sigmoidf_(float x) { return 1.0f / (1.0f + expf(-x)); }

__global__ void lstm_update(int use_gates, float* __restrict__ out, int wout) {
    int idx = blockIdx.x * 256 + threadIdx.x;       // G*H
    if (idx >= GG * HH) return;
    int g = idx >> 9, k = idx & 511;
    float ig, fg, gg, og;
    if (use_gates) {
        const float* row = d_gates + (size_t)g * H4;
        ig = row[k]; fg = row[HH + k]; gg = row[2 * HH + k]; og = row[3 * HH + k];
    } else {
        ig = d_bias[k]; fg = d_bias[HH + k]; gg = d_bias[2 * HH + k]; og = d_bias[3 * HH + k];
    }
    float c = d_c[idx];
    c = sigmoidf_(fg) * c + sigmoidf_(ig) * tanhf(gg);
    float h = sigmoidf_(og) * tanhf(c);
    d_c[idx] = c;
    d_xc[g * K2 + k] = h;                            // h half of q_star (fp32)
    d_xh[g * K2 + k] = __float2half(h);              // fp16 for GEMM
    if (wout) out[g * K2 + k] = h;                   // final-iter output h half
}

// -------- u_g = W_m^T h_g  (16 graphs / block, 256 thr, k split in half) -----
__global__ __launch_bounds__(256) void compute_u(const float* __restrict__ W_m) {
    int g0 = blockIdx.x * 16;
    int tid = threadIdx.x;
    int d = tid & 127, kh = tid >> 7;                // k half: [0,256) or [256,512)
    int khbase = kh * 256;
    float acc[16];
#pragma unroll
    for (int gg = 0; gg < 16; gg++) acc[gg] = 0.0f;
    __shared__ float hs[2][16][16];
    __shared__ float red[2][16][128];
    int i1 = tid & 127;
    int i2 = i1 + 128;
    for (int k0 = 0; k0 < 256; k0 += 16) {
        hs[kh][i1 >> 4][i1 & 15] = d_xc[(g0 + (i1 >> 4)) * K2 + khbase + k0 + (i1 & 15)];
        hs[kh][i2 >> 4][i2 & 15] = d_xc[(g0 + (i2 >> 4)) * K2 + khbase + k0 + (i2 & 15)];
        __syncthreads();
#pragma unroll
        for (int kk = 0; kk < 16; kk++) {
            float w = W_m[(khbase + k0 + kk) * DD + d];
#pragma unroll
            for (int gg = 0; gg < 16; gg++) acc[gg] += w * hs[kh][gg][kk];
        }
        __syncthreads();
    }
#pragma unroll
    for (int gg = 0; gg < 16; gg++) red[kh][gg][d] = acc[gg];
    __syncthreads();
#pragma unroll
    for (int j = 0; j < 8; j++) {
        int e = tid + j * 256;                        // 2048 outputs
        int gg = e >> 7, dd = e & 127;
        d_u[(g0 + gg) * DD + dd] = red[0][gg][dd] + red[1][gg][dd];
    }
}

// ------------------------- beta = b_m . h (warp/graph) -----------------------
__global__ __launch_bounds__(256) void compute_beta(const float* __restrict__ b_m) {
    int w = threadIdx.x >> 5, lane = threadIdx.x & 31;
    int g = blockIdx.x * 8 + w;
    const float4* h4 = (const float4*)(d_xc + (size_t)g * K2);
    const float4* b4 = (const float4*)b_m;
    float p = 0.0f;
#pragma unroll
    for (int i = 0; i < 4; i++) {
        float4 hv = h4[lane + i * 32];
        float4 bv = b4[lane + i * 32];
        p += hv.x * bv.x + hv.y * bv.y + hv.z * bv.z + hv.w * bv.w;
    }
    p += __shfl_xor_sync(0xffffffffu, p, 16);
    p += __shfl_xor_sync(0xffffffffu, p, 8);
    p += __shfl_xor_sync(0xffffffffu, p, 4);
    p += __shfl_xor_sync(0xffffffffu, p, 2);
    p += __shfl_xor_sync(0xffffffffu, p, 1);
    if (lane == 0) d_beta[g] = p;
}

// ------- fused attention: single pass online softmax + weighted feature sum --
__global__ __launch_bounds__(256) void attention_fused(const float* __restrict__ f) {
    int g = blockIdx.x;
    int s0 = d_start[g], s1 = d_start[g + 1];
    __shared__ __align__(16) float u_s[128];
    __shared__ __align__(16) float wacc[8][128];
    __shared__ float wm_s[8], wS_s[8], fac_s[8];
    __shared__ float inv_s;
    int tid = threadIdx.x, lane = tid & 31, warp = tid >> 5;

    if (tid < 128) u_s[tid] = d_u[g * DD + tid];
    float beta = d_beta[g];
    __syncthreads();

    float4 uv = ((const float4*)u_s)[lane];
    float m = -3.4e38f, S = 0.0f;
    float4 acc = make_float4(0.f, 0.f, 0.f, 0.f);

    for (int n = s0 + warp; n < s1; n += 8) {
        float4 fv = *(const float4*)(f + (size_t)n * DD + lane * 4);
        float p = fv.x * uv.x + fv.y * uv.y + fv.z * uv.z + fv.w * uv.w;
        p += __shfl_xor_sync(0xffffffffu, p, 16);
        p += __shfl_xor_sync(0xffffffffu, p, 8);
        p += __shfl_xor_sync(0xffffffffu, p, 4);
        p += __shfl_xor_sync(0xffffffffu, p, 2);
        p += __shfl_xor_sync(0xffffffffu, p, 1);
        float e = p + beta;
        float mn = fmaxf(m, e);
        float alpha = expf(m - mn);
        float w = expf(e - mn);
        S = S * alpha + w;
        acc.x = acc.x * alpha + w * fv.x;
        acc.y = acc.y * alpha + w * fv.y;
        acc.z = acc.z * alpha + w * fv.z;
        acc.w = acc.w * alpha + w * fv.w;
        m = mn;
    }
    if (lane == 0) { wm_s[warp] = m; wS_s[warp] = S; }
    ((float4*)wacc[warp])[lane] = acc;
    __syncthreads();

    if (tid == 0) {
        float M = -3.4e38f;
#pragma unroll
        for (int w = 0; w < 8; w++)
            if (wS_s[w] > 0.0f) M = fmaxf(M, wm_s[w]);
        float Z = 0.0f;
#pragma unroll
        for (int w = 0; w < 8; w++) {
            float sc = (wS_s[w] > 0.0f) ? expf(wm_s[w] - M) : 0.0f;
            fac_s[w] = sc;
            Z += sc * wS_s[w];
        }
        float inv = 1.0f / (Z + 1e-7f);
        inv_s = inv;
        d_tg[g] = Z * inv;
    }
    __syncthreads();

    if (tid < 128) {
        float inv = inv_s;
        float s = 0.0f;
#pragma unroll
        for (int w = 0; w < 8; w++) s += wacc[w][tid] * fac_s[w];
        d_s[g * DD + tid] = s * inv;
    }
}

// ---------------- r_g = W_m s_g + t_g b_m  (8 graphs / block) ----------------
__global__ __launch_bounds__(512) void compute_r(const float* __restrict__ b_m,
                                                 float* __restrict__ out, int wout) {
    int g0 = blockIdx.x * 8;
    int k = threadIdx.x;                              // 0..511
    __shared__ float ss[8][128];
    {
        int i = k;        ss[i >> 7][i & 127] = d_s[(g0 + (i >> 7)) * DD + (i & 127)];
        int i2 = k + 512; ss[i2 >> 7][i2 & 127] = d_s[(g0 + (i2 >> 7)) * DD + (i2 & 127)];
    }
    __syncthreads();
    float bm = b_m[k];
    float acc[8];
#pragma unroll
    for (int gg = 0; gg < 8; gg++) acc[gg] = d_tg[g0 + gg] * bm;
    for (int d = 0; d < DD; d++) {
        float w = d_Wmt[d * HH + k];
#pragma unroll
        for (int gg = 0; gg < 8; gg++) acc[gg] += w * ss[gg][d];
    }
#pragma unroll
    for (int gg = 0; gg < 8; gg++) {
        d_xc[(g0 + gg) * K2 + HH + k] = acc[gg];
        d_xh[(g0 + gg) * K2 + HH + k] = __float2half(acc[gg]);
        if (wout) out[(g0 + gg) * K2 + HH + k] = acc[gg];
    }
}

// ------------------------------ launcher ------------------------------------
extern "C" void kernel_launch(void* const* d_in, const int* in_sizes, int n_in,
                              void* d_out, int out_size) {
    const float* features = (const float*)d_in[0];
    const int*   gi       = (const int*)d_in[1];
    const float* W_m      = (const float*)d_in[2];
    const float* b_m      = (const float*)d_in[3];
    const float* W_ih     = (const float*)d_in[4];
    const float* W_hh     = (const float*)d_in[5];
    const float* b_ih     = (const float*)d_in[6];
    const float* b_hh     = (const float*)d_in[7];
    float* out = (float*)d_out;

    cudaFuncSetAttribute(gemm_h<512, 512, true>,
                         cudaFuncAttributeMaxDynamicSharedMemorySize, GEMM_SMEM);
    cudaFuncSetAttribute(gemm_h<0, 1024, false>,
                         cudaFuncAttributeMaxDynamicSharedMemorySize, GEMM_SMEM);

    prep_wc<<<(H4 * K2) / 256, 256>>>(W_ih, W_hh);
    prep_misc<<<(GG * HH) / 256, 256>>>(b_ih, b_hh, W_m);
    graph_offsets<<<(GG + 1 + 255) / 256, 256>>>(gi);

    for (int t = 0; t < 3; t++) {
        if (t == 1) {
            compute_gbias<<<GG / 8, 256>>>();
            gemm_h<512, 512, true><<<dim3(H4 / 256, GG / 128), 256, GEMM_SMEM>>>();
        } else if (t == 2) {
            gemm_h<0, 1024, false><<<dim3(H4 / 256, GG / 128), 256, GEMM_SMEM>>>();
        }
        int wout = (t == 2) ? 1 : 0;
        lstm_update<<<(GG * HH) / 256, 256>>>(t > 0 ? 1 : 0, out, wout);
        compute_u<<<GG / 16, 256>>>(W_m);
        compute_beta<<<GG / 8, 256>>>(b_m);
        attention_fused<<<GG, 256>>>(features);
        compute_r<<<GG / 8, 512>>>(b_m, out, wout);
    }
}

// round 7
// speedup vs baseline: 3.0144x; 1.1674x over previous
#include <cuda_runtime.h>
#include <cuda_fp16.h>
#include <cstdint>
#include <math.h>

// Problem constants (fixed instance)
#define NN 131072   // nodes
#define DD 128      // feature dim
#define GG 2048     // graphs
#define HH 512      // hidden
#define H4 2048     // 4*H
#define K2 1024     // 2*H (combined gemm K)

// ---------------- scratch (static device globals; no allocation) -------------
__device__ __half d_Wch[H4 * K2];      // combined gate weights [4H, 2H], fp16
__device__ float d_bias[H4];           // b_ih + b_hh
__device__ float d_gbias[H4];          // bias + h0 @ Wc[:, :H]^T  (t=1 shared part)
__device__ float d_Wmt[DD * HH];       // W_m transposed
__device__ __half d_xh[GG * K2];       // fp16 q_star = [h | r] (GEMM A operand)
__device__ __half d_fh[NN * DD];       // fp16 features
__device__ float d_c[GG * HH];         // LSTM cell state (t=1 -> t=2)
__device__ float d_h0[HH];             // shared h after t=0
__device__ float d_c0[HH];             // shared c after t=0
__device__ float d_u0[DD];             // shared u after t=0
__device__ float d_beta0[1];           // shared beta after t=0
__device__ float d_gates[GG * H4];     // gates scratch
__device__ float d_u[GG * DD];         // u_g = W_m^T h_g
__device__ float d_beta[GG];           // b_m . h_g
__device__ float d_s[GG * DD];         // s_g = sum_n a_n f_n (normalized)
__device__ float d_tg[GG];             // t_g = exp_sum/(exp_sum+eps)
__device__ int   d_start[GG + 1];      // segment offsets

// ------------------------------ prep kernels --------------------------------
__global__ void prep_wc(const float* __restrict__ W_ih, const float* __restrict__ W_hh) {
    int idx = blockIdx.x * 256 + threadIdx.x;
    if (idx >= H4 * K2) return;
    int j = idx >> 10, k = idx & 1023;
    float v = W_ih[idx];
    if (k < HH) v += W_hh[j * HH + k];
    d_Wch[idx] = __float2half(v);
}

__global__ void prep_misc(const float* __restrict__ b_ih, const float* __restrict__ b_hh,
                          const float* __restrict__ W_m) {
    int idx = blockIdx.x * 256 + threadIdx.x;
    if (idx < H4)      d_bias[idx] = b_ih[idx] + b_hh[idx];
    if (idx < DD * HH) {
        int d = idx >> 9, k = idx & 511;
        d_Wmt[idx] = W_m[k * DD + d];
    }
}

__global__ void feat2h(const float* __restrict__ f) {
    int idx = blockIdx.x * 256 + threadIdx.x;          // 1 thread = 8 floats
    const float4* f4 = (const float4*)f;
    float4 a = f4[idx * 2], b = f4[idx * 2 + 1];
    __half2 h0 = __floats2half2_rn(a.x, a.y);
    __half2 h1 = __floats2half2_rn(a.z, a.w);
    __half2 h2 = __floats2half2_rn(b.x, b.y);
    __half2 h3 = __floats2half2_rn(b.z, b.w);
    uint4 packed;
    packed.x = *(uint32_t*)&h0; packed.y = *(uint32_t*)&h1;
    packed.z = *(uint32_t*)&h2; packed.w = *(uint32_t*)&h3;
    ((uint4*)d_fh)[idx] = packed;
}

__global__ void graph_offsets(const int* __restrict__ gi) {
    int g = blockIdx.x * 256 + threadIdx.x;
    if (g > GG) return;
    int lo = 0, hi = NN;
    while (lo < hi) { int mid = (lo + hi) >> 1; if (gi[mid] < g) lo = mid + 1; else hi = mid; }
    d_start[g] = lo;
}

__device__ __forceinline__ float sigmoidf_(float x) { return 1.0f / (1.0f + expf(-x)); }

// ---- t=0: gates = bias identical across graphs -> one shared h0,c0,u0,beta0 --
__global__ __launch_bounds__(512) void init0(const float* __restrict__ W_m,
                                             const float* __restrict__ b_m) {
    __shared__ float h_s[HH];
    __shared__ float red[4][DD];
    __shared__ float br[512];
    int tid = threadIdx.x;                             // 0..511, = k
    float ig = d_bias[tid], fg = d_bias[HH + tid];
    float gg = d_bias[2 * HH + tid], og = d_bias[3 * HH + tid];
    float c = sigmoidf_(ig) * tanhf(gg);               // c_prev = 0
    float h = sigmoidf_(og) * tanhf(c);
    h_s[tid] = h;
    d_h0[tid] = h;
    d_c0[tid] = c;
    br[tid] = b_m[tid] * h;
    __syncthreads();
    // u0[d] = sum_k W_m[k,d] * h0[k]
    int d = tid & 127, q = tid >> 7;                   // q in 0..3
    float acc = 0.0f;
    for (int k = q * 128; k < q * 128 + 128; k++)
        acc += W_m[k * DD + d] * h_s[k];
    red[q][d] = acc;
    __syncthreads();
    if (tid < DD) d_u0[tid] = red[0][tid] + red[1][tid] + red[2][tid] + red[3][tid];
    // beta0 = b_m . h0
    for (int s = 256; s > 0; s >>= 1) {
        if (tid < s) br[tid] += br[tid + s];
        __syncthreads();
    }
    if (tid == 0) d_beta0[0] = br[0];
}

__global__ void bcast0() {
    int idx = blockIdx.x * 256 + threadIdx.x;          // GG*DD
    d_u[idx] = d_u0[idx & 127];
    if (idx < GG) d_beta[idx] = d_beta0[0];
}

// gbias[j] = bias[j] + sum_{k<H} h0[k] * Wc[j,k]
__global__ __launch_bounds__(256) void compute_gbias() {
    int j = blockIdx.x * 8 + (threadIdx.x >> 5);
    int lane = threadIdx.x & 31;
    const __half2* w2 = (const __half2*)(d_Wch + (size_t)j * K2);
    const float2* h02 = (const float2*)d_h0;
    float p = 0.0f;
#pragma unroll
    for (int i = lane; i < HH / 2; i += 32) {
        float2 wf = __half22float2(w2[i]);
        float2 hf = h02[i];
        p += wf.x * hf.x + wf.y * hf.y;
    }
    p += __shfl_xor_sync(0xffffffffu, p, 16);
    p += __shfl_xor_sync(0xffffffffu, p, 8);
    p += __shfl_xor_sync(0xffffffffu, p, 4);
    p += __shfl_xor_sync(0xffffffffu, p, 2);
    p += __shfl_xor_sync(0xffffffffu, p, 1);
    if (lane == 0) d_gbias[j] = d_bias[j] + p;
}

// --------- gates GEMM (fp16 mma.sync m16n8k16): gates = xh @ Wch^T + bias ----
#define SROWH 40
#define A_STGH (128 * SROWH)
#define B_STGH (256 * SROWH)
#define GEMM_SMEM ((2 * A_STGH + 2 * B_STGH) * 2)

__device__ __forceinline__ void cpa16(uint32_t daddr, const void* g) {
    asm volatile("cp.async.cg.shared.global [%0], [%1], 16;" :: "r"(daddr), "l"(g));
}

__device__ __forceinline__ void load_stage(uint32_t sA, uint32_t sB,
                                           int bm, int bn, int k0, int tid) {
#pragma unroll
    for (int j = 0; j < 2; j++) {
        int a = tid + j * 256;
        int row = a >> 2, c = a & 3;
        cpa16(sA + (uint32_t)(row * SROWH + c * 8) * 2,
              d_xh + (size_t)(bm + row) * K2 + k0 + c * 8);
    }
#pragma unroll
    for (int j = 0; j < 4; j++) {
        int b = tid + j * 256;
        int row = b >> 2, c = b & 3;
        cpa16(sB + (uint32_t)(row * SROWH + c * 8) * 2,
              d_Wch + (size_t)(bn + row) * K2 + k0 + c * 8);
    }
    asm volatile("cp.async.commit_group;");
}

template <int KOFF, int KLEN, bool GB>
__global__ __launch_bounds__(256, 1) void gemm_h() {
    extern __shared__ __half smh[];
    __half* Abase = smh;
    __half* Bbase = smh + 2 * A_STGH;
    uint32_t sAu, sBu;
    {
        uint64_t t;
        asm("cvta.to.shared.u64 %0, %1;" : "=l"(t) : "l"(Abase));
        sAu = (uint32_t)t;
        asm("cvta.to.shared.u64 %0, %1;" : "=l"(t) : "l"(Bbase));
        sBu = (uint32_t)t;
    }
    const int tid = threadIdx.x, lane = tid & 31, warp = tid >> 5;
    const int wm = (warp & 1) * 64, wn = (warp >> 1) * 64;
    const int g = lane >> 2, t = lane & 3;
    const int bm = blockIdx.y * 128, bn = blockIdx.x * 256;

    float acc[4][8][4];
#pragma unroll
    for (int a = 0; a < 4; a++)
#pragma unroll
        for (int b = 0; b < 8; b++)
#pragma unroll
            for (int c = 0; c < 4; c++) acc[a][b][c] = 0.0f;

    load_stage(sAu, sBu, bm, bn, KOFF, tid);

    const int NIT = KLEN / 32;
    for (int it = 0; it < NIT; it++) {
        int buf = it & 1;
        if (it + 1 < NIT) {
            int nb = buf ^ 1;
            load_stage(sAu + nb * A_STGH * 2, sBu + nb * B_STGH * 2,
                       bm, bn, KOFF + (it + 1) * 32, tid);
            asm volatile("cp.async.wait_group 1;");
        } else {
            asm volatile("cp.async.wait_group 0;");
        }
        __syncthreads();

        const __half* Ab = Abase + buf * A_STGH;
        const __half* Bb = Bbase + buf * B_STGH;
#pragma unroll
        for (int kb = 0; kb < 32; kb += 16) {
            unsigned af[4][4], bf[8][2];
#pragma unroll
            for (int mi = 0; mi < 4; mi++) {
                const __half* ba = &Ab[(wm + mi * 16 + g) * SROWH + kb + 2 * t];
                af[mi][0] = *(const uint32_t*)(ba);
                af[mi][1] = *(const uint32_t*)(ba + 8 * SROWH);
                af[mi][2] = *(const uint32_t*)(ba + 8);
                af[mi][3] = *(const uint32_t*)(ba + 8 * SROWH + 8);
            }
#pragma unroll
            for (int ni = 0; ni < 8; ni++) {
                const __half* bb = &Bb[(wn + ni * 8 + g) * SROWH + kb + 2 * t];
                bf[ni][0] = *(const uint32_t*)(bb);
                bf[ni][1] = *(const uint32_t*)(bb + 8);
            }
#pragma unroll
            for (int mi = 0; mi < 4; mi++)
#pragma unroll
                for (int ni = 0; ni < 8; ni++)
                    asm volatile(
                        "mma.sync.aligned.m16n8k16.row.col.f32.f16.f16.f32 "
                        "{%0,%1,%2,%3}, {%4,%5,%6,%7}, {%8,%9}, {%0,%1,%2,%3};"
                        : "+f"(acc[mi][ni][0]), "+f"(acc[mi][ni][1]),
                          "+f"(acc[mi][ni][2]), "+f"(acc[mi][ni][3])
                        : "r"(af[mi][0]), "r"(af[mi][1]), "r"(af[mi][2]), "r"(af[mi][3]),
                          "r"(bf[ni][0]), "r"(bf[ni][1]));
        }
        __syncthreads();
    }

    const float* bias = GB ? d_gbias : d_bias;
#pragma unroll
    for (int mi = 0; mi < 4; mi++) {
        int r0 = bm + wm + mi * 16 + g;
#pragma unroll
        for (int ni = 0; ni < 8; ni++) {
            int cc = bn + wn + ni * 8 + 2 * t;
            float b0 = bias[cc], b1 = bias[cc + 1];
            float2 v0 = make_float2(acc[mi][ni][0] + b0, acc[mi][ni][1] + b1);
            float2 v1 = make_float2(acc[mi][ni][2] + b0, acc[mi][ni][3] + b1);
            *(float2*)&d_gates[(size_t)r0 * H4 + cc] = v0;
            *(float2*)&d_gates[(size_t)(r0 + 8) * H4 + cc] = v1;
        }
    }
}

// ------- fused LSTM + u + beta: 16 graphs / block, 256 threads ---------------
// use_c0=1: read shared d_c0 (t=1); use_c0=0: read per-graph d_c (t=2).
// NOTE: d_c0/d_c are selected INSIDE device code (device symbols cannot be
// passed as kernel args from host).
__global__ __launch_bounds__(256) void lstm_u_beta(int use_c0, int wc,
                                                   const float* __restrict__ W_m,
                                                   const float* __restrict__ b_m,
                                                   float* __restrict__ out, int wout) {
    __shared__ float h_s[16][HH];                      // 32 KB
    __shared__ float red[2][16][DD];                   // 16 KB
    int g0 = blockIdx.x * 16;
    int tid = threadIdx.x;
    int k2 = tid * 2;                                  // this thread's k pair

    const float* cbase = use_c0 ? d_c0 : d_c;
    size_t cstride = use_c0 ? 0 : HH;

    // ---- phase 1: LSTM for 16 graphs, 2 cells each ----
#pragma unroll
    for (int gg = 0; gg < 16; gg++) {
        int g = g0 + gg;
        const float* row = d_gates + (size_t)g * H4;
        float2 ig = *(const float2*)(row + k2);
        float2 fg = *(const float2*)(row + HH + k2);
        float2 gv = *(const float2*)(row + 2 * HH + k2);
        float2 og = *(const float2*)(row + 3 * HH + k2);
        float2 cp = *(const float2*)(cbase + (size_t)g * cstride + k2);
        float c0n = sigmoidf_(fg.x) * cp.x + sigmoidf_(ig.x) * tanhf(gv.x);
        float c1n = sigmoidf_(fg.y) * cp.y + sigmoidf_(ig.y) * tanhf(gv.y);
        float h0n = sigmoidf_(og.x) * tanhf(c0n);
        float h1n = sigmoidf_(og.y) * tanhf(c1n);
        *(float2*)&h_s[gg][k2] = make_float2(h0n, h1n);
        __half2* xh2 = (__half2*)(d_xh + (size_t)g * K2 + k2);
        *xh2 = __floats2half2_rn(h0n, h1n);
        if (wc) *(float2*)&d_c[(size_t)g * HH + k2] = make_float2(c0n, c1n);
        if (wout) *(float2*)&out[(size_t)g * K2 + k2] = make_float2(h0n, h1n);
    }
    __syncthreads();

    // ---- phase 2: u_g = W_m^T h_g  (d = tid&127, k half by tid>>7) ----
    {
        int d = tid & 127, kh = tid >> 7;
        int kb = kh * 256;
        float acc[16];
#pragma unroll
        for (int gg = 0; gg < 16; gg++) acc[gg] = 0.0f;
        for (int k = 0; k < 256; k++) {
            float w = W_m[(kb + k) * DD + d];
#pragma unroll
            for (int gg = 0; gg < 16; gg++) acc[gg] += w * h_s[gg][kb + k];
        }
#pragma unroll
        for (int gg = 0; gg < 16; gg++) red[kh][gg][d] = acc[gg];
    }
    __syncthreads();
#pragma unroll
    for (int j = 0; j < 8; j++) {
        int e = tid + j * 256;                         // 2048 outputs
        int gg = e >> 7, dd = e & 127;
        d_u[(g0 + gg) * DD + dd] = red[0][gg][dd] + red[1][gg][dd];
    }

    // ---- phase 3: beta = b_m . h (2 graphs per warp) ----
    {
        int w = tid >> 5, lane = tid & 31;
#pragma unroll
        for (int j = 0; j < 2; j++) {
            int gg = w * 2 + j;
            float p = 0.0f;
            for (int k = lane; k < HH; k += 32) p += b_m[k] * h_s[gg][k];
            p += __shfl_xor_sync(0xffffffffu, p, 16);
            p += __shfl_xor_sync(0xffffffffu, p, 8);
            p += __shfl_xor_sync(0xffffffffu, p, 4);
            p += __shfl_xor_sync(0xffffffffu, p, 2);
            p += __shfl_xor_sync(0xffffffffu, p, 1);
            if (lane == 0) d_beta[g0 + gg] = p;
        }
    }
}

// ------- fused attention: single pass online softmax + weighted feature sum --
__global__ __launch_bounds__(256) void attention_fused() {
    int g = blockIdx.x;
    int s0 = d_start[g], s1 = d_start[g + 1];
    __shared__ __align__(16) float u_s[128];
    __shared__ __align__(16) float wacc[8][128];
    __shared__ float wm_s[8], wS_s[8], fac_s[8];
    __shared__ float inv_s;
    int tid = threadIdx.x, lane = tid & 31, warp = tid >> 5;

    if (tid < 128) u_s[tid] = d_u[g * DD + tid];
    float beta = d_beta[g];
    __syncthreads();

    float4 uv = ((const float4*)u_s)[lane];
    float m = -3.4e38f, S = 0.0f;
    float4 acc = make_float4(0.f, 0.f, 0.f, 0.f);

    for (int n = s0 + warp; n < s1; n += 8) {
        uint2 raw = *(const uint2*)(d_fh + (size_t)n * DD + lane * 4);
        float2 f01 = __half22float2(*(__half2*)&raw.x);
        float2 f23 = __half22float2(*(__half2*)&raw.y);
        float p = f01.x * uv.x + f01.y * uv.y + f23.x * uv.z + f23.y * uv.w;
        p += __shfl_xor_sync(0xffffffffu, p, 16);
        p += __shfl_xor_sync(0xffffffffu, p, 8);
        p += __shfl_xor_sync(0xffffffffu, p, 4);
        p += __shfl_xor_sync(0xffffffffu, p, 2);
        p += __shfl_xor_sync(0xffffffffu, p, 1);
        float e = p + beta;
        float mn = fmaxf(m, e);
        float alpha = expf(m - mn);
        float w = expf(e - mn);
        S = S * alpha + w;
        acc.x = acc.x * alpha + w * f01.x;
        acc.y = acc.y * alpha + w * f01.y;
        acc.z = acc.z * alpha + w * f23.x;
        acc.w = acc.w * alpha + w * f23.y;
        m = mn;
    }
    if (lane == 0) { wm_s[warp] = m; wS_s[warp] = S; }
    ((float4*)wacc[warp])[lane] = acc;
    __syncthreads();

    if (tid == 0) {
        float M = -3.4e38f;
#pragma unroll
        for (int w = 0; w < 8; w++)
            if (wS_s[w] > 0.0f) M = fmaxf(M, wm_s[w]);
        float Z = 0.0f;
#pragma unroll
        for (int w = 0; w < 8; w++) {
            float sc = (wS_s[w] > 0.0f) ? expf(wm_s[w] - M) : 0.0f;
            fac_s[w] = sc;
            Z += sc * wS_s[w];
        }
        float inv = 1.0f / (Z + 1e-7f);
        inv_s = inv;
        d_tg[g] = Z * inv;
    }
    __syncthreads();

    if (tid < 128) {
        float inv = inv_s;
        float s = 0.0f;
#pragma unroll
        for (int w = 0; w < 8; w++) s += wacc[w][tid] * fac_s[w];
        d_s[g * DD + tid] = s * inv;
    }
}

// ---------------- r_g = W_m s_g + t_g b_m  (8 graphs / block) ----------------
__global__ __launch_bounds__(512) void compute_r(const float* __restrict__ b_m,
                                                 float* __restrict__ out, int wout) {
    int g0 = blockIdx.x * 8;
    int k = threadIdx.x;                              // 0..511
    __shared__ float ss[8][128];
    {
        int i = k;        ss[i >> 7][i & 127] = d_s[(g0 + (i >> 7)) * DD + (i & 127)];
        int i2 = k + 512; ss[i2 >> 7][i2 & 127] = d_s[(g0 + (i2 >> 7)) * DD + (i2 & 127)];
    }
    __syncthreads();
    float bm = b_m[k];
    float acc[8];
#pragma unroll
    for (int gg = 0; gg < 8; gg++) acc[gg] = d_tg[g0 + gg] * bm;
    for (int d = 0; d < DD; d++) {
        float w = d_Wmt[d * HH + k];
#pragma unroll
        for (int gg = 0; gg < 8; gg++) acc[gg] += w * ss[gg][d];
    }
#pragma unroll
    for (int gg = 0; gg < 8; gg++) {
        d_xh[(g0 + gg) * K2 + HH + k] = __float2half(acc[gg]);
        if (wout) out[(g0 + gg) * K2 + HH + k] = acc[gg];
    }
}

// ------------------------------ launcher ------------------------------------
extern "C" void kernel_launch(void* const* d_in, const int* in_sizes, int n_in,
                              void* d_out, int out_size) {
    const float* features = (const float*)d_in[0];
    const int*   gi       = (const int*)d_in[1];
    const float* W_m      = (const float*)d_in[2];
    const float* b_m      = (const float*)d_in[3];
    const float* W_ih     = (const float*)d_in[4];
    const float* W_hh     = (const float*)d_in[5];
    const float* b_ih     = (const float*)d_in[6];
    const float* b_hh     = (const float*)d_in[7];
    float* out = (float*)d_out;

    cudaFuncSetAttribute(gemm_h<512, 512, true>,
                         cudaFuncAttributeMaxDynamicSharedMemorySize, GEMM_SMEM);
    cudaFuncSetAttribute(gemm_h<0, 1024, false>,
                         cudaFuncAttributeMaxDynamicSharedMemorySize, GEMM_SMEM);

    prep_wc<<<(H4 * K2) / 256, 256>>>(W_ih, W_hh);
    prep_misc<<<(DD * HH) / 256, 256>>>(b_ih, b_hh, W_m);
    graph_offsets<<<(GG + 1 + 255) / 256, 256>>>(gi);
    feat2h<<<(NN * DD / 8) / 256, 256>>>(features);

    // t = 0 (all graphs share h0/c0/u0/beta0)
    init0<<<1, 512>>>(W_m, b_m);
    bcast0<<<(GG * DD) / 256, 256>>>();
    attention_fused<<<GG, 256>>>();
    compute_r<<<GG / 8, 512>>>(b_m, out, 0);

    // t = 1 (K=512 GEMM on r only; h0 folded into gbias; c from shared c0)
    compute_gbias<<<GG / 8, 256>>>();
    gemm_h<512, 512, true><<<dim3(H4 / 256, GG / 128), 256, GEMM_SMEM>>>();
    lstm_u_beta<<<GG / 16, 256>>>(1, 1, W_m, b_m, out, 0);
    attention_fused<<<GG, 256>>>();
    compute_r<<<GG / 8, 512>>>(b_m, out, 0);

    // t = 2 (full K=1024 GEMM; final outputs)
    gemm_h<0, 1024, false><<<dim3(H4 / 256, GG / 128), 256, GEMM_SMEM>>>();
    lstm_u_beta<<<GG / 16, 256>>>(0, 0, W_m, b_m, out, 1);
    attention_fused<<<GG, 256>>>();
    compute_r<<<GG / 8, 512>>>(b_m, out, 1);
}